// round 14
// baseline (speedup 1.0000x reference)
#include <cuda_runtime.h>
#include <cuda_fp16.h>
#include <math.h>
#include <stdint.h>

// B=2, S=2048, T=4096, D_IN=2048, H=16, QK_HEAD=128, V_HEAD=128, KV_RANK=512
#define TOKS 4096
#define SEQ  2048

// ---------------------------------------------------------------------------
// Scratch (fp16)
// ---------------------------------------------------------------------------
__device__ __half g_xh[(size_t)TOKS * 2048];
__device__ __half g_qh[(size_t)TOKS * 2048];
__device__ __half g_kvh[(size_t)TOKS * 576];
__device__ __half g_kvch[(size_t)TOKS * 512];
__device__ __half g_kpeh[(size_t)TOKS * 64];
__device__ __half g_kvdech[(size_t)TOKS * 3072];
__device__ __half g_attnh[(size_t)TOKS * 2048];
__device__ __half g_wqh[(size_t)2048 * 2048];
__device__ __half g_wkvah[(size_t)2048 * 576];
__device__ __half g_wkvbh[(size_t)512 * 3072];
__device__ __half g_wouth[(size_t)2048 * 2048];

// ---------------------------------------------------------------------------
// Helpers
// ---------------------------------------------------------------------------
__device__ __forceinline__ uint32_t h2_to_u32(__half2 h) {
    union { __half2 h2; uint32_t u; } cvt;
    cvt.h2 = h;
    return cvt.u;
}

__device__ __forceinline__ void mma_f16(float* d, const uint32_t* a, const uint32_t* b) {
    asm volatile(
        "mma.sync.aligned.m16n8k16.row.col.f32.f16.f16.f32 "
        "{%0,%1,%2,%3}, {%4,%5,%6,%7}, {%8,%9}, {%0,%1,%2,%3};\n"
        : "+f"(d[0]), "+f"(d[1]), "+f"(d[2]), "+f"(d[3])
        : "r"(a[0]), "r"(a[1]), "r"(a[2]), "r"(a[3]), "r"(b[0]), "r"(b[1]));
}
__device__ __forceinline__ void ldsm_x4(uint32_t* r, uint32_t addr) {
    asm volatile("ldmatrix.sync.aligned.m8n8.x4.shared.b16 {%0,%1,%2,%3}, [%4];\n"
                 : "=r"(r[0]), "=r"(r[1]), "=r"(r[2]), "=r"(r[3]) : "r"(addr));
}
__device__ __forceinline__ void ldsm_x4_t(uint32_t* r, uint32_t addr) {
    asm volatile("ldmatrix.sync.aligned.m8n8.x4.trans.shared.b16 {%0,%1,%2,%3}, [%4];\n"
                 : "=r"(r[0]), "=r"(r[1]), "=r"(r[2]), "=r"(r[3]) : "r"(addr));
}
__device__ __forceinline__ void cp_async16(void* smem_ptr, const void* gptr) {
    uint32_t saddr = (uint32_t)__cvta_generic_to_shared(smem_ptr);
    asm volatile("cp.async.cg.shared.global [%0], [%1], 16;\n"
                 :: "r"(saddr), "l"(gptr) : "memory");
}
__device__ __forceinline__ void cp_async16z(void* smem_ptr, const void* gptr, int sz) {
    uint32_t saddr = (uint32_t)__cvta_generic_to_shared(smem_ptr);
    asm volatile("cp.async.cg.shared.global [%0], [%1], 16, %2;\n"
                 :: "r"(saddr), "l"(gptr), "r"(sz) : "memory");
}
__device__ __forceinline__ void cp_commit() {
    asm volatile("cp.async.commit_group;\n" ::: "memory");
}
template <int N>
__device__ __forceinline__ void cp_wait() {
    asm volatile("cp.async.wait_group %0;\n" :: "n"(N) : "memory");
}

// ---------------------------------------------------------------------------
// Pre-pass kernels
// ---------------------------------------------------------------------------
__global__ __launch_bounds__(256)
void prep_half(const float* __restrict__ in, __half* __restrict__ out,
               float scale, int n4)
{
    const int i = blockIdx.x * 256 + threadIdx.x;
    if (i >= n4) return;
    const float4 v = ((const float4*)in)[i];
    __half2* o = (__half2*)out + (size_t)i * 2;
    o[0] = __floats2half2_rn(v.x * scale, v.y * scale);
    o[1] = __floats2half2_rn(v.z * scale, v.w * scale);
}

// Fused cast for three scale-1 weights (wkv_a | wkv_b | out_proj)
__global__ __launch_bounds__(256)
void prep3(const float* __restrict__ a, __half* __restrict__ ao, int na4,
           const float* __restrict__ b, __half* __restrict__ bo, int nb4,
           const float* __restrict__ c, __half* __restrict__ co, int nc4)
{
    const int i = blockIdx.x * 256 + threadIdx.x;
    const float* src;
    __half* dst;
    int j;
    if (i < na4)              { src = a; dst = ao; j = i; }
    else if (i < na4 + nb4)   { src = b; dst = bo; j = i - na4; }
    else if (i < na4 + nb4 + nc4) { src = c; dst = co; j = i - na4 - nb4; }
    else return;
    const float4 v = ((const float4*)src)[j];
    __half2* o = (__half2*)dst + (size_t)j * 2;
    o[0] = __floats2half2_rn(v.x, v.y);
    o[1] = __floats2half2_rn(v.z, v.w);
}

// ---------------------------------------------------------------------------
// FP16 GEMM: C[M,N] = A[M,K] @ B[K,N].
// BM=BN=128, BK=64, 256 thr / 8 warps, 2 CTAs/SM, 3-stage cp.async pipeline.
// R14: A-fragment loads software-pipelined one mt ahead (asm volatile blocks
// compiler reordering, so scheduling is done by hand).
// ---------------------------------------------------------------------------
#define G2_ASTR 72
#define G2_BSTR 136
#define G2_AH (128 * G2_ASTR)
#define G2_BH (64 * G2_BSTR)
#define G2_STG (G2_AH + G2_BH)
#define GEMM_SMEM (3 * G2_STG * 2)

template <bool HALF_OUT>
__global__ __launch_bounds__(256, 2)
void gemm_f16(const __half* __restrict__ A, const __half* __restrict__ B,
              void* __restrict__ Cv, int M, int N, int K)
{
    extern __shared__ __half smh[];
    const uint32_t smb = (uint32_t)__cvta_generic_to_shared(smh);

    const int t = threadIdx.x;
    const int lane = t & 31, wid = t >> 5;
    const int g = lane >> 2, tig = lane & 3;
    const int wm = wid >> 2;
    const int wn = wid & 3;
    const int row0 = blockIdx.y * 128;
    const int col0 = blockIdx.x * 128;

    float acc[4][4][4];
#pragma unroll
    for (int mt = 0; mt < 4; mt++)
#pragma unroll
        for (int nt = 0; nt < 4; nt++)
#pragma unroll
            for (int i = 0; i < 4; i++) acc[mt][nt][i] = 0.f;

    const int nkt = K >> 6;

#define G2_STAGE(buf, k0)                                                      \
    {                                                                          \
        __half* As = smh + (buf) * G2_STG;                                     \
        __half* Bs = As + G2_AH;                                               \
        _Pragma("unroll")                                                      \
        for (int i = 0; i < 4; i++) {                                          \
            const int id = t + i * 256;                                        \
            const int ar = id >> 3, ac = (id & 7) * 8;                         \
            cp_async16(As + ar * G2_ASTR + ac,                                 \
                       A + (size_t)(row0 + ar) * K + (k0) + ac);               \
            const int br = id >> 4, bc = (id & 15) * 8;                        \
            const int col = col0 + bc;                                         \
            const int sz = (col + 8 <= N) ? 16 : 0;                            \
            cp_async16z(Bs + br * G2_BSTR + bc,                                \
                        B + (size_t)((k0) + br) * N + (sz ? col : 0), sz);     \
        }                                                                      \
    }

    G2_STAGE(0, 0);
    cp_commit();
    G2_STAGE(1, 64);
    cp_commit();

    for (int kt = 0; kt < nkt; kt++) {
        if (kt + 1 < nkt) { cp_wait<1>(); } else { cp_wait<0>(); }
        __syncthreads();

        if (kt + 2 < nkt) {
            const int pb = (kt + 2) % 3;
            G2_STAGE(pb, (kt + 2) << 6);
            cp_commit();
        }

        const uint32_t abase = smb + ((kt % 3) * G2_STG) * 2;
        const uint32_t bbase = abase + G2_AH * 2;

#pragma unroll
        for (int kh = 0; kh < 2; kh++) {
            uint32_t bf[4][2][2];
            const uint32_t baddr =
                bbase + (uint32_t)((kh * 32 + lane) * G2_BSTR + wn * 32) * 2;
#pragma unroll
            for (int nt = 0; nt < 4; nt++) {
                uint32_t rr[4];
                ldsm_x4_t(rr, baddr + nt * 16);
                bf[nt][0][0] = rr[0]; bf[nt][0][1] = rr[1];
                bf[nt][1][0] = rr[2]; bf[nt][1][1] = rr[3];
            }
            const uint32_t aaddr =
                abase + (uint32_t)((wm * 64 + (lane & 15)) * G2_ASTR +
                                   (lane >> 4) * 8 + kh * 32) * 2;
            // A-fragment double buffer: prefetch mt+1 before consuming mt
            uint32_t af[2][2][4];
            ldsm_x4(af[0][0], aaddr);
            ldsm_x4(af[0][1], aaddr + 32);
#pragma unroll
            for (int mt = 0; mt < 4; mt++) {
                const int cur = mt & 1;
                if (mt < 3) {
                    ldsm_x4(af[cur ^ 1][0], aaddr + (mt + 1) * (16 * G2_ASTR * 2));
                    ldsm_x4(af[cur ^ 1][1], aaddr + (mt + 1) * (16 * G2_ASTR * 2) + 32);
                }
#pragma unroll
                for (int nt = 0; nt < 4; nt++) {
                    mma_f16(acc[mt][nt], af[cur][0], bf[nt][0]);
                    mma_f16(acc[mt][nt], af[cur][1], bf[nt][1]);
                }
            }
        }
    }

#pragma unroll
    for (int mt = 0; mt < 4; mt++) {
        const int gr0 = row0 + wm * 64 + mt * 16 + g;
#pragma unroll
        for (int nt = 0; nt < 4; nt++) {
            const int gc = col0 + wn * 32 + nt * 8 + 2 * tig;
            if (gc < N) {
                if (HALF_OUT) {
                    __half* C = (__half*)Cv;
                    *(__half2*)(C + (size_t)gr0 * N + gc) =
                        __floats2half2_rn(acc[mt][nt][0], acc[mt][nt][1]);
                    *(__half2*)(C + (size_t)(gr0 + 8) * N + gc) =
                        __floats2half2_rn(acc[mt][nt][2], acc[mt][nt][3]);
                } else {
                    float* C = (float*)Cv;
                    *(float2*)(C + (size_t)gr0 * N + gc) =
                        make_float2(acc[mt][nt][0], acc[mt][nt][1]);
                    *(float2*)(C + (size_t)(gr0 + 8) * N + gc) =
                        make_float2(acc[mt][nt][2], acc[mt][nt][3]);
                }
            }
        }
    }
}

// ---------------------------------------------------------------------------
// RMSNorm / RoPE (unchanged)
// ---------------------------------------------------------------------------
__global__ __launch_bounds__(128)
void rmsnorm_h(const __half* __restrict__ kv, const float* __restrict__ w,
               __half* __restrict__ out)
{
    __shared__ float red[4];
    const int tok = blockIdx.x;
    const int t = threadIdx.x;
    const __half* row = kv + (size_t)tok * 576;
    float v[4];
    float s = 0.0f;
#pragma unroll
    for (int u = 0; u < 4; u++) {
        v[u] = __half2float(row[t + u * 128]);
        s = fmaf(v[u], v[u], s);
    }
#pragma unroll
    for (int off = 16; off > 0; off >>= 1)
        s += __shfl_down_sync(0xffffffffu, s, off);
    if ((t & 31) == 0) red[t >> 5] = s;
    __syncthreads();
    const float tot = red[0] + red[1] + red[2] + red[3];
    const float r = rsqrtf(tot * (1.0f / 512.0f) + 1e-6f);
    __half* orow = out + (size_t)tok * 512;
#pragma unroll
    for (int u = 0; u < 4; u++) {
        const int idx = t + u * 128;
        orow[idx] = __float2half_rn(v[u] * r * w[idx]);
    }
}

__global__ __launch_bounds__(512)
void rope_qh(__half* __restrict__ q)
{
    const int tok = blockIdx.x;
    const int h = threadIdx.x >> 5;
    const int i = threadIdx.x & 31;
    const int s = tok & (SEQ - 1);
    const float e = (float)(2 * i) * (1.0f / 64.0f);
    const float freq = 1.0f / powf(10000.0f, e);
    float sn, c;
    sincosf((float)s * freq, &sn, &c);
    __half2* p = (__half2*)(q + (size_t)tok * 2048 + h * 128 + 64) + i;
    const float2 v = __half22float2(*p);
    *p = __floats2half2_rn(v.x * c - v.y * sn, v.y * c + v.x * sn);
}

__global__ __launch_bounds__(32)
void rope_kh(const __half* __restrict__ kv, __half* __restrict__ kpe)
{
    const int tok = blockIdx.x;
    const int i = threadIdx.x;
    const int s = tok & (SEQ - 1);
    const float e = (float)(2 * i) * (1.0f / 64.0f);
    const float freq = 1.0f / powf(10000.0f, e);
    float sn, c;
    sincosf((float)s * freq, &sn, &c);
    const float x1 = __half2float(kv[(size_t)tok * 576 + 512 + 2 * i]);
    const float x2 = __half2float(kv[(size_t)tok * 576 + 512 + 2 * i + 1]);
    ((__half2*)(kpe + (size_t)tok * 64))[i] =
        __floats2half2_rn(x1 * c - x2 * sn, x2 * c + x1 * sn);
}

// ---------------------------------------------------------------------------
// Flash attention v3 (unchanged from R13)
// ---------------------------------------------------------------------------
#define FV_Q  0
#define FV_K0 17408
#define FV_K1 26112
#define FV_V0 34816
#define FV_V1 43520
#define FLASH_SMEM (52224 * 2)

__global__ __launch_bounds__(256)
void flash_v3(const __half* __restrict__ qh, const __half* __restrict__ kvd,
              const __half* __restrict__ kpe, __half* __restrict__ o)
{
    extern __shared__ __half smh[];
    const uint32_t smb = (uint32_t)__cvta_generic_to_shared(smh);

    const int t = threadIdx.x;
    const int lane = t & 31, w = t >> 5;
    const int g = lane >> 2, tig = lane & 3;
    const int qb = blockIdx.x, h = blockIdx.y, b = blockIdx.z;
    const int q0 = qb * 128;

#pragma unroll
    for (int i = 0; i < 8; i++) {
        const int id = t + i * 256;
        const int r = id >> 4, c = (id & 15) * 8;
        *(uint4*)(smh + FV_Q + r * 136 + c) =
            *(const uint4*)(qh + (size_t)(b * SEQ + q0 + r) * 2048 + h * 128 + c);
    }

#define FV_STAGE(koff, voff, ktile)                                            \
    {                                                                          \
        const int k0_ = (ktile) * 64;                                          \
        _Pragma("unroll")                                                      \
        for (int i = 0; i < 4; i++) {                                          \
            const int id = t + i * 256;                                        \
            const int r = id >> 4, c8 = id & 15;                               \
            const size_t tok = (size_t)(b * SEQ + k0_ + r);                    \
            const __half* ks = (c8 < 8)                                        \
                ? kvd + (tok * 16 + h) * 192 + c8 * 8                          \
                : kpe + tok * 64 + (c8 - 8) * 8;                               \
            cp_async16(smh + (koff) + r * 136 + c8 * 8, ks);                   \
            cp_async16(smh + (voff) + r * 136 + c8 * 8,                        \
                       kvd + (tok * 16 + h) * 192 + 64 + c8 * 8);              \
        }                                                                      \
    }

    FV_STAGE(FV_K0, FV_V0, 0);
    cp_commit();

    float oacc[16][4];
#pragma unroll
    for (int nt = 0; nt < 16; nt++)
#pragma unroll
        for (int i = 0; i < 4; i++) oacc[nt][i] = 0.f;

    float m0 = -1e30f, m1 = -1e30f, l0 = 0.f, l1 = 0.f;

    const uint32_t qByte =
        smb + (uint32_t)((FV_Q + (w * 16 + (lane & 15)) * 136 + (lane >> 4) * 8)) * 2;
    const uint32_t kRow = (uint32_t)((lane & 7) * 136 + (lane >> 3) * 8) * 2;
    const uint32_t vRow = (uint32_t)(lane * 136) * 2;

    const int nkt = 2 * (qb + 1);
    for (int kt = 0; kt < nkt; kt++) {
        cp_wait<0>();
        __syncthreads();
        const int bsel = kt & 1;
        if (kt + 1 < nkt) {
            if (bsel) { FV_STAGE(FV_K0, FV_V0, kt + 1); }
            else      { FV_STAGE(FV_K1, FV_V1, kt + 1); }
            cp_commit();
        }

        // Final k-tile: warps 0-3 fully masked -> skip (barriers already done).
        if (kt == nkt - 1 && w < 4) continue;

        const uint32_t kBase = smb + (bsel ? FV_K1 : FV_K0) * 2 + kRow;
        const uint32_t vBase = smb + (bsel ? FV_V1 : FV_V0) * 2 + vRow;
        const int k0 = kt * 64;

        float sacc[8][4];
#pragma unroll
        for (int nt = 0; nt < 8; nt++)
#pragma unroll
            for (int i = 0; i < 4; i++) sacc[nt][i] = 0.f;

#pragma unroll
        for (int dch = 0; dch < 4; dch++) {
            uint32_t a0[4], a1[4];
            ldsm_x4(a0, qByte + dch * 64);
            ldsm_x4(a1, qByte + dch * 64 + 32);
#pragma unroll
            for (int ng = 0; ng < 2; ng++) {
                uint32_t kb[4][2][2];
#pragma unroll
                for (int j = 0; j < 4; j++) {
                    uint32_t rr[4];
                    ldsm_x4(rr, kBase + (ng * 4 + j) * (8 * 136 * 2) + dch * 64);
                    kb[j][0][0] = rr[0]; kb[j][0][1] = rr[1];
                    kb[j][1][0] = rr[2]; kb[j][1][1] = rr[3];
                }
#pragma unroll
                for (int j = 0; j < 4; j++) {
                    mma_f16(sacc[ng * 4 + j], a0, kb[j][0]);
                    mma_f16(sacc[ng * 4 + j], a1, kb[j][1]);
                }
            }
        }

        if (kt >= nkt - 2) {
            const int row0 = q0 + w * 16 + g;
#pragma unroll
            for (int nt = 0; nt < 8; nt++) {
                const int col = k0 + nt * 8 + 2 * tig;
                if (col     > row0)     sacc[nt][0] = -1e30f;
                if (col + 1 > row0)     sacc[nt][1] = -1e30f;
                if (col     > row0 + 8) sacc[nt][2] = -1e30f;
                if (col + 1 > row0 + 8) sacc[nt][3] = -1e30f;
            }
        }

        float mx0 = m0, mx1 = m1;
#pragma unroll
        for (int nt = 0; nt < 8; nt++) {
            mx0 = fmaxf(mx0, fmaxf(sacc[nt][0], sacc[nt][1]));
            mx1 = fmaxf(mx1, fmaxf(sacc[nt][2], sacc[nt][3]));
        }
        mx0 = fmaxf(mx0, __shfl_xor_sync(0xffffffffu, mx0, 1));
        mx0 = fmaxf(mx0, __shfl_xor_sync(0xffffffffu, mx0, 2));
        mx1 = fmaxf(mx1, __shfl_xor_sync(0xffffffffu, mx1, 1));
        mx1 = fmaxf(mx1, __shfl_xor_sync(0xffffffffu, mx1, 2));
        const float f0 = exp2f(m0 - mx0);
        const float f1 = exp2f(m1 - mx1);
        float s0 = 0.f, s1 = 0.f;
        uint32_t ph[8][2];
#pragma unroll
        for (int nt = 0; nt < 8; nt++) {
            const float p00 = exp2f(sacc[nt][0] - mx0);
            const float p01 = exp2f(sacc[nt][1] - mx0);
            const float p10 = exp2f(sacc[nt][2] - mx1);
            const float p11 = exp2f(sacc[nt][3] - mx1);
            s0 += p00 + p01;
            s1 += p10 + p11;
            ph[nt][0] = h2_to_u32(__floats2half2_rn(p00, p01));
            ph[nt][1] = h2_to_u32(__floats2half2_rn(p10, p11));
        }
        s0 += __shfl_xor_sync(0xffffffffu, s0, 1);
        s0 += __shfl_xor_sync(0xffffffffu, s0, 2);
        s1 += __shfl_xor_sync(0xffffffffu, s1, 1);
        s1 += __shfl_xor_sync(0xffffffffu, s1, 2);
        l0 = l0 * f0 + s0;
        l1 = l1 * f1 + s1;
        m0 = mx0;
        m1 = mx1;
#pragma unroll
        for (int nt = 0; nt < 16; nt++) {
            oacc[nt][0] *= f0; oacc[nt][1] *= f0;
            oacc[nt][2] *= f1; oacc[nt][3] *= f1;
        }

#pragma unroll
        for (int vch = 0; vch < 2; vch++) {
            const uint32_t A0[4] = {ph[4 * vch + 0][0], ph[4 * vch + 0][1],
                                    ph[4 * vch + 1][0], ph[4 * vch + 1][1]};
            const uint32_t A1[4] = {ph[4 * vch + 2][0], ph[4 * vch + 2][1],
                                    ph[4 * vch + 3][0], ph[4 * vch + 3][1]};
#pragma unroll
            for (int ng = 0; ng < 4; ng++) {
                uint32_t vb[4][2][2];
#pragma unroll
                for (int j = 0; j < 4; j++) {
                    uint32_t rr[4];
                    ldsm_x4_t(rr, vBase + vch * (32 * 136 * 2) + (ng * 4 + j) * 16);
                    vb[j][0][0] = rr[0]; vb[j][0][1] = rr[1];
                    vb[j][1][0] = rr[2]; vb[j][1][1] = rr[3];
                }
#pragma unroll
                for (int j = 0; j < 4; j++) {
                    mma_f16(oacc[ng * 4 + j], A0, vb[j][0]);
                    mma_f16(oacc[ng * 4 + j], A1, vb[j][1]);
                }
            }
        }
    }

    const float inv0 = 1.0f / l0;
    const float inv1 = 1.0f / l1;
    const size_t r0 = (size_t)(b * SEQ + q0 + w * 16 + g) * 2048 + h * 128;
    const size_t r1 = (size_t)(b * SEQ + q0 + w * 16 + g + 8) * 2048 + h * 128;
#pragma unroll
    for (int nt = 0; nt < 16; nt++) {
        const int col = nt * 8 + 2 * tig;
        *(__half2*)(o + r0 + col) =
            __floats2half2_rn(oacc[nt][0] * inv0, oacc[nt][1] * inv0);
        *(__half2*)(o + r1 + col) =
            __floats2half2_rn(oacc[nt][2] * inv1, oacc[nt][3] * inv1);
    }
}

// ---------------------------------------------------------------------------
// Launch (idx 3 = gemm_f16 G1 for the ncu capture window)
// ---------------------------------------------------------------------------
extern "C" void kernel_launch(void* const* d_in, const int* in_sizes, int n_in,
                              void* d_out, int out_size)
{
    (void)in_sizes; (void)n_in; (void)out_size;
    const float* x          = (const float*)d_in[0];
    const float* w_query    = (const float*)d_in[1];
    const float* wkv_a      = (const float*)d_in[2];
    const float* wkv_b      = (const float*)d_in[3];
    const float* kv_norm_w  = (const float*)d_in[4];
    const float* out_proj_w = (const float*)d_in[5];
    float* out = (float*)d_out;

    __half *xh, *qh, *kvh, *kvch, *kpeh, *kvdech, *attnh, *wqh, *wkvah, *wkvbh, *wouth;
    cudaGetSymbolAddress((void**)&xh,     g_xh);
    cudaGetSymbolAddress((void**)&qh,     g_qh);
    cudaGetSymbolAddress((void**)&kvh,    g_kvh);
    cudaGetSymbolAddress((void**)&kvch,   g_kvch);
    cudaGetSymbolAddress((void**)&kpeh,   g_kpeh);
    cudaGetSymbolAddress((void**)&kvdech, g_kvdech);
    cudaGetSymbolAddress((void**)&attnh,  g_attnh);
    cudaGetSymbolAddress((void**)&wqh,    g_wqh);
    cudaGetSymbolAddress((void**)&wkvah,  g_wkvah);
    cudaGetSymbolAddress((void**)&wkvbh,  g_wkvbh);
    cudaGetSymbolAddress((void**)&wouth,  g_wouth);

    cudaFuncSetAttribute(gemm_f16<true>,
                         cudaFuncAttributeMaxDynamicSharedMemorySize, GEMM_SMEM);
    cudaFuncSetAttribute(gemm_f16<false>,
                         cudaFuncAttributeMaxDynamicSharedMemorySize, GEMM_SMEM);
    cudaFuncSetAttribute(flash_v3,
                         cudaFuncAttributeMaxDynamicSharedMemorySize, FLASH_SMEM);

    // 1/sqrt(128) * log2(e): flash softmax runs in base-2 domain
    const float qscale = 0.08838834764831845f * 1.44269504088896340736f;

    // idx0: x cast
    prep_half<<<(TOKS * 2048 / 4 + 255) / 256, 256>>>(x, xh, 1.0f, TOKS * 2048 / 4);
    // idx1: w_query cast (scale folded)
    prep_half<<<(2048 * 2048 / 4 + 255) / 256, 256>>>(w_query, wqh, qscale, 2048 * 2048 / 4);
    // idx2: fused cast of wkv_a | wkv_b | out_proj
    {
        const int na4 = 2048 * 576 / 4;
        const int nb4 = 512 * 3072 / 4;
        const int nc4 = 2048 * 2048 / 4;
        const int tot = na4 + nb4 + nc4;
        prep3<<<(tot + 255) / 256, 256>>>(wkv_a, wkvah, na4,
                                          wkv_b, wkvbh, nb4,
                                          out_proj_w, wouth, nc4);
    }
    // idx3: q = x @ (w_query*qscale)   <-- ncu capture lands here
    gemm_f16<true><<<dim3(16, 32), 256, GEMM_SMEM>>>(xh, wqh, qh, TOKS, 2048, 2048);
    // kv = x @ wkv_a
    gemm_f16<true><<<dim3(5, 32), 256, GEMM_SMEM>>>(xh, wkvah, kvh, TOKS, 576, 2048);
    // rope q_pe in place
    rope_qh<<<TOKS, 512>>>(qh);
    // rmsnorm latent
    rmsnorm_h<<<TOKS, 128>>>(kvh, kv_norm_w, kvch);
    // rope k_pe
    rope_kh<<<TOKS, 32>>>(kvh, kpeh);
    // kv_dec = kvc @ wkv_b
    gemm_f16<true><<<dim3(24, 32), 256, GEMM_SMEM>>>(kvch, wkvbh, kvdech, TOKS, 3072, 512);
    // causal flash attention
    flash_v3<<<dim3(SEQ / 128, 16, 2), 256, FLASH_SMEM>>>(qh, kvdech, kpeh, attnh);
    // out = attn @ out_proj_w
    gemm_f16<false><<<dim3(16, 32), 256, GEMM_SMEM>>>(attnh, wouth, out, TOKS, 2048, 2048);
}